// round 1
// baseline (speedup 1.0000x reference)
#include <cuda_runtime.h>
#include <math.h>

// Problem constants
#define Nn 16
#define Hh 112
#define Wd 112
#define Cc 128
#define Ho 110
#define Wo 110
#define Co 256
#define KK 1152                 // 3*3*128
#define MM (Nn*Ho*Wo)           // 193600
#define PIX (Nn*Hh*Wd)          // 200704

// Scratch (no allocations allowed)
__device__ float g_s[PIX];      // per-input-pixel sum of squares over channels
__device__ float g_xni[MM];     // 1/(sqrt(patch_sq)+qq) per output pixel
__device__ float g_ws[Co];      // 1/(||W_cout||+qq)
__device__ float g_ae[Co];      // p^2/100

// ---------------------------------------------------------------------------
// Kernel 1: per-output-channel weight norm inverse and exponent
// ---------------------------------------------------------------------------
__global__ void prep_w_kernel(const float* __restrict__ W,
                              const float* __restrict__ p,
                              const float* __restrict__ q) {
    int c = threadIdx.x;            // 0..255
    float sum = 0.0f;
    #pragma unroll 4
    for (int k = 0; k < KK; ++k) {
        float w = W[k * Co + c];
        sum = fmaf(w, w, sum);
    }
    float qq = q[0] * q[0] * 0.1f;
    g_ws[c] = 1.0f / (sqrtf(sum) + qq);
    g_ae[c] = p[c] * p[c] * 0.01f;
}

// ---------------------------------------------------------------------------
// Kernel 2: per input pixel, sum of x^2 over 128 channels. One warp per pixel.
// ---------------------------------------------------------------------------
__global__ void sumsq_kernel(const float* __restrict__ x) {
    int pix  = blockIdx.x * 8 + (threadIdx.x >> 5);
    int lane = threadIdx.x & 31;
    const float4* xp = reinterpret_cast<const float4*>(x + (size_t)pix * Cc);
    float4 v = xp[lane];            // 32 lanes * 4 = 128 channels
    float s = v.x * v.x + v.y * v.y + v.z * v.z + v.w * v.w;
    #pragma unroll
    for (int o = 16; o > 0; o >>= 1)
        s += __shfl_xor_sync(0xffffffffu, s, o);
    if (lane == 0) g_s[pix] = s;
}

// ---------------------------------------------------------------------------
// Kernel 3: 3x3 window sum of g_s -> inverse patch norm per output pixel
// ---------------------------------------------------------------------------
__global__ void xnorm_kernel(const float* __restrict__ q) {
    int idx = blockIdx.x * 256 + threadIdx.x;
    if (idx >= MM) return;
    int n = idx / (Ho * Wo);
    int r = idx % (Ho * Wo);
    int h = r / Wo;
    int w = r % Wo;
    const float* sp = g_s + ((size_t)n * Hh + h) * Wd + w;
    float sum = 0.0f;
    #pragma unroll
    for (int ky = 0; ky < 3; ++ky)
        sum += sp[ky * Wd] + sp[ky * Wd + 1] + sp[ky * Wd + 2];
    float qq = q[0] * q[0] * 0.1f;
    g_xni[idx] = 1.0f / (sqrtf(sum) + qq);
}

// ---------------------------------------------------------------------------
// Kernel 4: implicit-GEMM conv (fp32) + fused cosine-power epilogue.
// C[M=193600, 256] = A[M, 1152] * B[1152, 256]
//   A[m, k] = x[n, h+ky, w+kx, c]  (k = (ky*3+kx)*128 + c) — contiguous per tile
//   B       = W flattened [1152, 256]
// Block tile 128x128, K-tile 16, 256 threads, 8x8 per thread.
// ---------------------------------------------------------------------------
#define KTILES (KK / 16)   // 72

__global__ __launch_bounds__(256, 2)
void conv_gemm_kernel(const float* __restrict__ x,
                      const float* __restrict__ W,
                      const float* __restrict__ bias,
                      float* __restrict__ out) {
    __shared__ float As[16][128];   // [k][m] transposed
    __shared__ float Bs[16][128];   // [k][n]
    __shared__ int   rowBase[128];

    const int t  = threadIdx.x;
    const int m0 = blockIdx.x * 128;
    const int n0 = blockIdx.y * 128;

    // Row base pointers for the 128 M-rows of this block
    if (t < 128) {
        int m = m0 + t;
        int base = -1;
        if (m < MM) {
            int n = m / (Ho * Wo);
            int r = m % (Ho * Wo);
            int h = r / Wo;
            int w = r % Wo;
            base = ((n * Hh + h) * Wd + w) * Cc;
        }
        rowBase[t] = base;
    }
    __syncthreads();

    // Loader roles
    const int a_row = t >> 1;            // 0..127
    const int a_k   = (t & 1) * 8;       // 0 or 8
    const int abase = rowBase[a_row];    // cached in register
    const int b_row = t >> 4;            // 0..15
    const int b_col = (t & 15) * 8;      // 0..120

    // Compute roles
    const int tx = t & 15;
    const int ty = t >> 4;

    float acc[8][8];
    #pragma unroll
    for (int i = 0; i < 8; ++i)
        #pragma unroll
        for (int j = 0; j < 8; ++j) acc[i][j] = 0.0f;

    float4 na0, na1, nb0, nb1;
    const float4 z4 = make_float4(0.f, 0.f, 0.f, 0.f);

    // ---- load tile kt into registers ----
    #define LOAD_TILE(kt)                                                     \
    {                                                                         \
        int kglob = (kt) * 16;                                                \
        int g  = kglob >> 7;                                                  \
        int c0 = kglob & 127;                                                 \
        int ky = g / 3;                                                       \
        int kx = g - ky * 3;                                                  \
        int koff = (ky * Wd + kx) * Cc + c0;                                  \
        if (abase >= 0) {                                                     \
            const float* ap = x + abase + koff + a_k;                         \
            na0 = *reinterpret_cast<const float4*>(ap);                       \
            na1 = *reinterpret_cast<const float4*>(ap + 4);                   \
        } else { na0 = z4; na1 = z4; }                                        \
        const float* bp = W + (size_t)(kglob + b_row) * Co + n0 + b_col;      \
        nb0 = *reinterpret_cast<const float4*>(bp);                          \
        nb1 = *reinterpret_cast<const float4*>(bp + 4);                      \
    }

    #define STORE_TILE()                                                      \
    {                                                                         \
        As[a_k + 0][a_row] = na0.x; As[a_k + 1][a_row] = na0.y;              \
        As[a_k + 2][a_row] = na0.z; As[a_k + 3][a_row] = na0.w;              \
        As[a_k + 4][a_row] = na1.x; As[a_k + 5][a_row] = na1.y;              \
        As[a_k + 6][a_row] = na1.z; As[a_k + 7][a_row] = na1.w;              \
        *reinterpret_cast<float4*>(&Bs[b_row][b_col])     = nb0;             \
        *reinterpret_cast<float4*>(&Bs[b_row][b_col + 4]) = nb1;             \
    }

    LOAD_TILE(0);
    STORE_TILE();
    __syncthreads();

    for (int kt = 0; kt < KTILES; ++kt) {
        if (kt + 1 < KTILES) LOAD_TILE(kt + 1);   // prefetch into registers

        #pragma unroll
        for (int kk = 0; kk < 16; ++kk) {
            const float4* As4 = reinterpret_cast<const float4*>(&As[kk][0]);
            const float4* Bs4 = reinterpret_cast<const float4*>(&Bs[kk][0]);
            float4 a0 = As4[ty];
            float4 a1 = As4[ty + 16];
            float4 b0 = Bs4[tx];
            float4 b1 = Bs4[tx + 16];
            float av[8] = {a0.x, a0.y, a0.z, a0.w, a1.x, a1.y, a1.z, a1.w};
            float bv[8] = {b0.x, b0.y, b0.z, b0.w, b1.x, b1.y, b1.z, b1.w};
            #pragma unroll
            for (int i = 0; i < 8; ++i)
                #pragma unroll
                for (int j = 0; j < 8; ++j)
                    acc[i][j] = fmaf(av[i], bv[j], acc[i][j]);
        }
        __syncthreads();
        if (kt + 1 < KTILES) {
            STORE_TILE();
        }
        __syncthreads();
    }

    // ---- fused epilogue ----
    const int ncol0 = n0 + tx * 4;
    const int ncol1 = n0 + 64 + tx * 4;
    float4 ws0 = *reinterpret_cast<const float4*>(&g_ws[ncol0]);
    float4 ws1 = *reinterpret_cast<const float4*>(&g_ws[ncol1]);
    float4 ae0 = *reinterpret_cast<const float4*>(&g_ae[ncol0]);
    float4 ae1 = *reinterpret_cast<const float4*>(&g_ae[ncol1]);
    float4 bb0 = *reinterpret_cast<const float4*>(&bias[ncol0]);
    float4 bb1 = *reinterpret_cast<const float4*>(&bias[ncol1]);
    float wsv[8] = {ws0.x, ws0.y, ws0.z, ws0.w, ws1.x, ws1.y, ws1.z, ws1.w};
    float aev[8] = {ae0.x, ae0.y, ae0.z, ae0.w, ae1.x, ae1.y, ae1.z, ae1.w};
    float bbv[8] = {bb0.x, bb0.y, bb0.z, bb0.w, bb1.x, bb1.y, bb1.z, bb1.w};

    #pragma unroll
    for (int i = 0; i < 8; ++i) {
        int m = m0 + ((i < 4) ? (ty * 4 + i) : (64 + ty * 4 + i - 4));
        if (m >= MM) continue;
        float xn = g_xni[m];
        float res[8];
        #pragma unroll
        for (int j = 0; j < 8; ++j) {
            float f  = acc[i][j] + bbv[j];
            float y  = f * xn * wsv[j];
            float ay = fabsf(y) + 1e-12f;
            float r  = __expf(aev[j] * __logf(ay));
            res[j]   = copysignf(r, f);
        }
        float* op = out + (size_t)m * Co;
        *reinterpret_cast<float4*>(op + ncol0) = make_float4(res[0], res[1], res[2], res[3]);
        *reinterpret_cast<float4*>(op + ncol1) = make_float4(res[4], res[5], res[6], res[7]);
    }
    #undef LOAD_TILE
    #undef STORE_TILE
}

// ---------------------------------------------------------------------------
extern "C" void kernel_launch(void* const* d_in, const int* in_sizes, int n_in,
                              void* d_out, int out_size) {
    const float* x = (const float*)d_in[0];
    const float* W = (const float*)d_in[1];
    const float* b = (const float*)d_in[2];
    const float* p = (const float*)d_in[3];
    const float* q = (const float*)d_in[4];
    float* out = (float*)d_out;

    prep_w_kernel<<<1, 256>>>(W, p, q);
    sumsq_kernel<<<PIX / 8, 256>>>(x);
    xnorm_kernel<<<(MM + 255) / 256, 256>>>(q);

    dim3 grid((MM + 127) / 128, Co / 128);
    conv_gemm_kernel<<<grid, 256>>>(x, W, b, out);
}

// round 4
// speedup vs baseline: 1.7639x; 1.7639x over previous
#include <cuda_runtime.h>
#include <cuda_fp16.h>
#include <cstdint>
#include <math.h>

// ---------------------------------------------------------------------------
// Problem constants
// ---------------------------------------------------------------------------
#define Nn 16
#define Hh 112
#define Wd 112
#define Cc 128
#define Ho 110
#define Wo 110
#define Co 256
#define KK 1152                 // 3*3*128
#define MM (Nn*Ho*Wo)           // 193600
#define PIX (Nn*Hh*Wd)          // 200704
#define XELT (PIX*Cc)           // 25,690,112
#define FIXCAP (1u << 21)       // 2M fixup entries
#define TAU 1e-5f               // |y| threshold for exact recompute

// ---------------------------------------------------------------------------
// Scratch (device globals; no allocations allowed)
// ---------------------------------------------------------------------------
__device__ float g_s[PIX];
__device__ float g_xni[MM];
__device__ float g_ws[Co];
__device__ float g_ae[Co];
__device__ __half g_Ah[XELT];        // x hi (fp16)
__device__ __half g_Al[XELT];        // x lo (fp16)
__device__ __half g_Bh[Co * KK];     // W hi, [n][k]
__device__ __half g_Bl[Co * KK];     // W lo, [n][k]
__device__ float  g_WT[Co * KK];     // W fp32 transposed [n][k] (for fixup)
__device__ uint32_t g_fix_list[FIXCAP];
__device__ uint32_t g_fix_cnt;

// ---------------------------------------------------------------------------
// Helpers
// ---------------------------------------------------------------------------
__device__ __forceinline__ uint32_t smem_u32(const void* p) {
    uint32_t a;
    asm("{ .reg .u64 t; cvta.to.shared.u64 t, %1; cvt.u32.u64 %0, t; }"
        : "=r"(a) : "l"(p));
    return a;
}
__device__ __forceinline__ uint32_t lds_u32(uint32_t a) {
    uint32_t v;
    asm volatile("ld.shared.b32 %0, [%1];" : "=r"(v) : "r"(a));
    return v;
}
#define CP16(dst, src) \
    asm volatile("cp.async.cg.shared.global [%0], [%1], 16;" \
                 :: "r"(dst), "l"(src) : "memory")

#define MMA_F16(cc, a, b)                                                     \
    asm volatile("mma.sync.aligned.m16n8k16.row.col.f32.f16.f16.f32 "        \
        "{%0,%1,%2,%3}, {%4,%5,%6,%7}, {%8,%9}, {%0,%1,%2,%3};"              \
        : "+f"((cc)[0]), "+f"((cc)[1]), "+f"((cc)[2]), "+f"((cc)[3])         \
        : "r"((a)[0]), "r"((a)[1]), "r"((a)[2]), "r"((a)[3]),                \
          "r"((b)[0]), "r"((b)[1]))

// 16B-chunk swizzle within a 128B row: conflict-free fragment loads
__device__ __forceinline__ uint32_t swz(uint32_t row, uint32_t chunk) {
    return row * 128u + ((chunk ^ (row & 7u)) << 4);
}

// ---------------------------------------------------------------------------
// Kernel 1: weight norms / exponents; resets fixup counter
// ---------------------------------------------------------------------------
__global__ void prep_w_kernel(const float* __restrict__ W,
                              const float* __restrict__ p,
                              const float* __restrict__ q) {
    __shared__ float red[256];
    int c = blockIdx.x, t = threadIdx.x;
    if (blockIdx.x == 0 && t == 0) g_fix_cnt = 0;
    float s = 0.0f;
    for (int k = t; k < KK; k += 256) {
        float w = W[k * Co + c];
        s = fmaf(w, w, s);
    }
    red[t] = s; __syncthreads();
    for (int o = 128; o > 0; o >>= 1) {
        if (t < o) red[t] += red[t + o];
        __syncthreads();
    }
    if (t == 0) {
        float qq = q[0] * q[0] * 0.1f;
        g_ws[c] = 1.0f / (sqrtf(red[0]) + qq);
        g_ae[c] = p[c] * p[c] * 0.01f;
    }
}

// ---------------------------------------------------------------------------
// Kernel 1b: split W -> fp16 hi/lo in [n][k] + fp32 transpose
// ---------------------------------------------------------------------------
__global__ void split_w_kernel(const float* __restrict__ W) {
    int k = blockIdx.x, n = threadIdx.x;
    float w = W[k * Co + n];
    __half h = __float2half_rn(w);
    __half l = __float2half_rn(w - __half2float(h));
    g_Bh[n * KK + k] = h;
    g_Bl[n * KK + k] = l;
    g_WT[n * KK + k] = w;
}

// ---------------------------------------------------------------------------
// Kernel 2: warp per pixel: split x -> fp16 hi/lo AND sum of squares
// ---------------------------------------------------------------------------
__global__ void split_x_sumsq_kernel(const float* __restrict__ x) {
    int pix  = blockIdx.x * 8 + (threadIdx.x >> 5);
    int lane = threadIdx.x & 31;
    size_t base = (size_t)pix * Cc + lane * 4;
    float4 v = *reinterpret_cast<const float4*>(x + base);

    __half hx = __float2half_rn(v.x), hy = __float2half_rn(v.y);
    __half hz = __float2half_rn(v.z), hw = __float2half_rn(v.w);
    __half lx = __float2half_rn(v.x - __half2float(hx));
    __half ly = __float2half_rn(v.y - __half2float(hy));
    __half lz = __float2half_rn(v.z - __half2float(hz));
    __half lw = __float2half_rn(v.w - __half2float(hw));

    __half2 h01 = __halves2half2(hx, hy), h23 = __halves2half2(hz, hw);
    __half2 l01 = __halves2half2(lx, ly), l23 = __halves2half2(lz, lw);
    *reinterpret_cast<__half2*>(g_Ah + base)     = h01;
    *reinterpret_cast<__half2*>(g_Ah + base + 2) = h23;
    *reinterpret_cast<__half2*>(g_Al + base)     = l01;
    *reinterpret_cast<__half2*>(g_Al + base + 2) = l23;

    float s = v.x * v.x + v.y * v.y + v.z * v.z + v.w * v.w;
    #pragma unroll
    for (int o = 16; o > 0; o >>= 1) s += __shfl_xor_sync(0xffffffffu, s, o);
    if (lane == 0) g_s[pix] = s;
}

// ---------------------------------------------------------------------------
// Kernel 3: 3x3 window sum -> inverse patch norm
// ---------------------------------------------------------------------------
__global__ void xnorm_kernel(const float* __restrict__ q) {
    int idx = blockIdx.x * 256 + threadIdx.x;
    if (idx >= MM) return;
    int n = idx / (Ho * Wo);
    int r = idx % (Ho * Wo);
    int h = r / Wo;
    int w = r % Wo;
    const float* sp = g_s + ((size_t)n * Hh + h) * Wd + w;
    float sum = 0.0f;
    #pragma unroll
    for (int ky = 0; ky < 3; ++ky)
        sum += sp[ky * Wd] + sp[ky * Wd + 1] + sp[ky * Wd + 2];
    float qq = q[0] * q[0] * 0.1f;
    g_xni[idx] = 1.0f / (sqrtf(sum) + qq);
}

// ---------------------------------------------------------------------------
// Kernel 4: fp16 3-pass split implicit GEMM (hh + lh + hl) + fused epilogue
//   Block 128M x 128N, K_STAGE=64 (18 stages), cp.async double buffer,
//   8 warps (4M x 2N), warp tile 32x64. Candidates |y|<TAU -> fixup list.
// ---------------------------------------------------------------------------
#define NST 18
#define RG_AH 0                 // per-stage regions: 128 rows x 128B
#define RG_AL 16384
#define RG_BH 32768
#define RG_BL 49152
#define STG 65536
#define SMEM_DYN (2 * STG)      // 131072
#define LISTCAP 8192

extern __shared__ char dsm[];

__global__ void __launch_bounds__(256)
conv_hmma_kernel(const float* __restrict__ bias, float* __restrict__ out) {
    __shared__ float s_ws[128], s_ae[128], s_bi[128];
    __shared__ int   s_rb[128];
    __shared__ uint32_t s_cnt, s_base;

    const uint32_t sbase = smem_u32(dsm);
    const int t    = threadIdx.x;
    const int w    = t >> 5;
    const int lane = t & 31;
    const int gid  = lane >> 2;
    const int tig  = lane & 3;
    const int m0   = blockIdx.x * 128;
    const int n0   = blockIdx.y * 128;

    if (t < 128) {
        int m = m0 + t;
        int base = 0;
        if (m < MM) {
            int n = m / (Ho * Wo);
            int r = m % (Ho * Wo);
            int h = r / Wo;
            int ww = r % Wo;
            base = ((n * Hh + h) * Wd + ww) * Cc;
        }
        s_rb[t] = base;
        s_ws[t] = g_ws[n0 + t];
        s_ae[t] = g_ae[n0 + t];
        s_bi[t] = bias[n0 + t];
    }
    if (t == 0) s_cnt = 0;
    __syncthreads();

    // staging roles: thread -> (row, chunk group of 4)
    const int srow  = t >> 1;
    const int sgrp  = (t & 1) * 4;
    const int abase = s_rb[srow];

    // warp tile
    const int wmo = (w & 3) * 32;
    const int wno = (w >> 2) * 64;

    float c[2][8][4];
    #pragma unroll
    for (int mi = 0; mi < 2; ++mi)
        #pragma unroll
        for (int ni = 0; ni < 8; ++ni)
            #pragma unroll
            for (int j = 0; j < 4; ++j) c[mi][ni][j] = 0.0f;

    #define STAGE_CP(s) do {                                                  \
        uint32_t bb = sbase + (uint32_t)((s) & 1) * STG;                      \
        int g  = (s) >> 1;                                                    \
        int cb = ((s) & 1) * 64;                                              \
        int ky = g / 3, kx = g - ky * 3;                                      \
        size_t axoff = (size_t)abase + (ky * Wd + kx) * Cc + cb;              \
        size_t bxoff = (size_t)(n0 + srow) * KK + (s) * 64;                   \
        _Pragma("unroll")                                                     \
        for (int i = 0; i < 4; ++i) {                                         \
            uint32_t ch = sgrp + i;                                           \
            uint32_t dof = swz(srow, ch);                                     \
            CP16(bb + RG_AH + dof, g_Ah + axoff + ch * 8);                    \
            CP16(bb + RG_AL + dof, g_Al + axoff + ch * 8);                    \
            CP16(bb + RG_BH + dof, g_Bh + bxoff + ch * 8);                    \
            CP16(bb + RG_BL + dof, g_Bl + bxoff + ch * 8);                    \
        }                                                                     \
        asm volatile("cp.async.commit_group;" ::: "memory");                  \
    } while (0)

    STAGE_CP(0);

    for (int s = 0; s < NST; ++s) {
        if (s + 1 < NST) {
            STAGE_CP(s + 1);
            asm volatile("cp.async.wait_group 1;" ::: "memory");
        } else {
            asm volatile("cp.async.wait_group 0;" ::: "memory");
        }
        __syncthreads();

        const uint32_t bb = sbase + (uint32_t)(s & 1) * STG;
        const uint32_t rA0 = wmo + gid, rA1 = wmo + 16 + gid;

        #pragma unroll
        for (int ks = 0; ks < 4; ++ks) {
            const uint32_t c0 = 2 * ks, c1 = 2 * ks + 1;
            const uint32_t in4 = 4 * tig;
            uint32_t ah[2][4], av[2][4], bv[8][2];

            // A hi fragments
            #pragma unroll
            for (int mi = 0; mi < 2; ++mi) {
                uint32_t r0 = (mi ? rA1 : rA0), r1 = r0 + 8;
                ah[mi][0] = lds_u32(bb + RG_AH + swz(r0, c0) + in4);
                ah[mi][1] = lds_u32(bb + RG_AH + swz(r1, c0) + in4);
                ah[mi][2] = lds_u32(bb + RG_AH + swz(r0, c1) + in4);
                ah[mi][3] = lds_u32(bb + RG_AH + swz(r1, c1) + in4);
            }
            // B hi fragments
            #pragma unroll
            for (int ni = 0; ni < 8; ++ni) {
                uint32_t rn = wno + ni * 8 + gid;
                bv[ni][0] = lds_u32(bb + RG_BH + swz(rn, c0) + in4);
                bv[ni][1] = lds_u32(bb + RG_BH + swz(rn, c1) + in4);
            }
            // pass 1: Ah * Bh
            #pragma unroll
            for (int mi = 0; mi < 2; ++mi)
                #pragma unroll
                for (int ni = 0; ni < 8; ++ni) MMA_F16(c[mi][ni], ah[mi], bv[ni]);

            // A lo fragments
            #pragma unroll
            for (int mi = 0; mi < 2; ++mi) {
                uint32_t r0 = (mi ? rA1 : rA0), r1 = r0 + 8;
                av[mi][0] = lds_u32(bb + RG_AL + swz(r0, c0) + in4);
                av[mi][1] = lds_u32(bb + RG_AL + swz(r1, c0) + in4);
                av[mi][2] = lds_u32(bb + RG_AL + swz(r0, c1) + in4);
                av[mi][3] = lds_u32(bb + RG_AL + swz(r1, c1) + in4);
            }
            // pass 2: Al * Bh
            #pragma unroll
            for (int mi = 0; mi < 2; ++mi)
                #pragma unroll
                for (int ni = 0; ni < 8; ++ni) MMA_F16(c[mi][ni], av[mi], bv[ni]);

            // B lo fragments (reuse bv)
            #pragma unroll
            for (int ni = 0; ni < 8; ++ni) {
                uint32_t rn = wno + ni * 8 + gid;
                bv[ni][0] = lds_u32(bb + RG_BL + swz(rn, c0) + in4);
                bv[ni][1] = lds_u32(bb + RG_BL + swz(rn, c1) + in4);
            }
            // pass 3: Ah * Bl
            #pragma unroll
            for (int mi = 0; mi < 2; ++mi)
                #pragma unroll
                for (int ni = 0; ni < 8; ++ni) MMA_F16(c[mi][ni], ah[mi], bv[ni]);
        }
        __syncthreads();
    }

    // ---- fused epilogue with candidate flagging ----
    uint32_t* s_list = (uint32_t*)dsm;   // stage buffers are dead now

    #pragma unroll
    for (int mi = 0; mi < 2; ++mi) {
        int r0 = m0 + wmo + mi * 16 + gid;
        int r1 = r0 + 8;
        bool v0 = (r0 < MM), v1 = (r1 < MM);
        float xn0 = v0 ? g_xni[r0] : 0.0f;
        float xn1 = v1 ? g_xni[r1] : 0.0f;
        #pragma unroll
        for (int ni = 0; ni < 8; ++ni) {
            int cl = wno + ni * 8 + 2 * tig;
            float bi0 = s_bi[cl], bi1 = s_bi[cl + 1];
            float ws0 = s_ws[cl], ws1 = s_ws[cl + 1];
            float ae0 = s_ae[cl], ae1 = s_ae[cl + 1];

            float f00 = c[mi][ni][0] + bi0;
            float f01 = c[mi][ni][1] + bi1;
            float f10 = c[mi][ni][2] + bi0;
            float f11 = c[mi][ni][3] + bi1;

            float y00 = f00 * xn0 * ws0;
            float y01 = f01 * xn0 * ws1;
            float y10 = f10 * xn1 * ws0;
            float y11 = f11 * xn1 * ws1;

            if (v0 && fabsf(y00) < TAU) {
                uint32_t i = atomicAdd(&s_cnt, 1u);
                if (i < LISTCAP) s_list[i] = ((uint32_t)r0 << 8) | (uint32_t)(n0 + cl);
            }
            if (v0 && fabsf(y01) < TAU) {
                uint32_t i = atomicAdd(&s_cnt, 1u);
                if (i < LISTCAP) s_list[i] = ((uint32_t)r0 << 8) | (uint32_t)(n0 + cl + 1);
            }
            if (v1 && fabsf(y10) < TAU) {
                uint32_t i = atomicAdd(&s_cnt, 1u);
                if (i < LISTCAP) s_list[i] = ((uint32_t)r1 << 8) | (uint32_t)(n0 + cl);
            }
            if (v1 && fabsf(y11) < TAU) {
                uint32_t i = atomicAdd(&s_cnt, 1u);
                if (i < LISTCAP) s_list[i] = ((uint32_t)r1 << 8) | (uint32_t)(n0 + cl + 1);
            }

            float a00 = fabsf(y00) + 1e-12f;
            float a01 = fabsf(y01) + 1e-12f;
            float a10 = fabsf(y10) + 1e-12f;
            float a11 = fabsf(y11) + 1e-12f;

            float o00 = copysignf(__expf(ae0 * __logf(a00)), f00);
            float o01 = copysignf(__expf(ae1 * __logf(a01)), f01);
            float o10 = copysignf(__expf(ae0 * __logf(a10)), f10);
            float o11 = copysignf(__expf(ae1 * __logf(a11)), f11);

            if (v0)
                *reinterpret_cast<float2*>(out + (size_t)r0 * Co + n0 + cl) =
                    make_float2(o00, o01);
            if (v1)
                *reinterpret_cast<float2*>(out + (size_t)r1 * Co + n0 + cl) =
                    make_float2(o10, o11);
        }
    }

    // flush candidate list to global
    __syncthreads();
    if (t == 0) {
        uint32_t cc = s_cnt < LISTCAP ? s_cnt : LISTCAP;
        s_cnt = cc;
        s_base = atomicAdd(&g_fix_cnt, cc);
    }
    __syncthreads();
    for (uint32_t i = t; i < s_cnt; i += 256) {
        uint32_t gidx = s_base + i;
        if (gidx < FIXCAP) g_fix_list[gidx] = s_list[i];
    }
    #undef STAGE_CP
}

// ---------------------------------------------------------------------------
// Kernel 5: exact fp32 recompute of flagged elements (warp per candidate)
// ---------------------------------------------------------------------------
__global__ void fixup_kernel(const float* __restrict__ x,
                             const float* __restrict__ bias,
                             float* __restrict__ out) {
    uint32_t total = g_fix_cnt;
    if (total > FIXCAP) total = FIXCAP;
    uint32_t wid   = (blockIdx.x * blockDim.x + threadIdx.x) >> 5;
    uint32_t nwarp = (gridDim.x * blockDim.x) >> 5;
    int lane = threadIdx.x & 31;

    for (uint32_t e = wid; e < total; e += nwarp) {
        uint32_t enc = g_fix_list[e];
        int m  = enc >> 8;
        int co = enc & 255;
        int n = m / (Ho * Wo);
        int r = m % (Ho * Wo);
        int h = r / Wo;
        int ww = r % Wo;
        int base = ((n * Hh + h) * Wd + ww) * Cc;

        float sum = 0.0f;
        #pragma unroll
        for (int g = 0; g < 9; ++g) {
            int ky = g / 3, kx = g - ky * 3;
            const float* xp = x + base + (ky * Wd + kx) * Cc;
            const float* wp = g_WT + (size_t)co * KK + g * 128;
            #pragma unroll
            for (int ci = 0; ci < 4; ++ci) {
                int cch = ci * 32 + lane;
                sum = fmaf(xp[cch], wp[cch], sum);
            }
        }
        #pragma unroll
        for (int o = 16; o > 0; o >>= 1)
            sum += __shfl_xor_sync(0xffffffffu, sum, o);

        if (lane == 0) {
            float f  = sum + bias[co];
            float y  = f * g_xni[m] * g_ws[co];
            float ay = fabsf(y) + 1e-12f;
            float rr = __expf(g_ae[co] * __logf(ay));
            out[(size_t)m * Co + co] = copysignf(rr, f);
        }
    }
}

// ---------------------------------------------------------------------------
extern "C" void kernel_launch(void* const* d_in, const int* in_sizes, int n_in,
                              void* d_out, int out_size) {
    const float* x = (const float*)d_in[0];
    const float* W = (const float*)d_in[1];
    const float* b = (const float*)d_in[2];
    const float* p = (const float*)d_in[3];
    const float* q = (const float*)d_in[4];
    float* out = (float*)d_out;

    prep_w_kernel<<<Co, 256>>>(W, p, q);
    split_w_kernel<<<KK, 256>>>(W);
    split_x_sumsq_kernel<<<PIX / 8, 256>>>(x);
    xnorm_kernel<<<(MM + 255) / 256, 256>>>(q);

    static bool attr_set = false;
    if (!attr_set) {
        cudaFuncSetAttribute(conv_hmma_kernel,
                             cudaFuncAttributeMaxDynamicSharedMemorySize, SMEM_DYN);
        attr_set = true;
    }
    dim3 grid((MM + 127) / 128, Co / 128);
    conv_hmma_kernel<<<grid, 256, SMEM_DYN>>>(b, out);

    fixup_kernel<<<512, 256>>>(x, b, out);
}